// round 3
// baseline (speedup 1.0000x reference)
#include <cuda_runtime.h>
#include <cstdint>

#define NN 100000
#define F1 128
#define FH 64
#define FO 32

// Scratch (no allocations allowed): ~78 MB of __device__ globals.
__device__ int   g_deg[NN];
__device__ float g_dinv[NN];
__device__ float g_h1[(size_t)NN * FH];   // x @ W1
__device__ float g_a1[(size_t)NN * FH];   // aggregated layer-1 (then relu'd in place)
__device__ float g_h3[(size_t)NN * FO];   // h2 @ W2
__device__ float g_a2[(size_t)NN * FO];   // aggregated layer-2

// ---------------------------------------------------------------------------
__global__ void k_init() {
    int stride = gridDim.x * blockDim.x;
    int i0 = blockIdx.x * blockDim.x + threadIdx.x;
    for (int j = i0; j < NN; j += stride) g_deg[j] = 0;
    for (long j = i0; j < (long)NN * FH; j += stride) g_a1[j] = 0.f;
    for (long j = i0; j < (long)NN * FO; j += stride) g_a2[j] = 0.f;
}

__global__ void k_deg(const int* __restrict__ ei, int E) {
    int i = blockIdx.x * blockDim.x + threadIdx.x;
    if (i < E) atomicAdd(&g_deg[ei[E + i]], 1);
}

__global__ void k_dinv() {
    int i = blockIdx.x * blockDim.x + threadIdx.x;
    if (i < NN) g_dinv[i] = rsqrtf((float)g_deg[i] + 1.0f);  // +1 self-loop
}

// ---------------------------------------------------------------------------
// GEMM1: h1[NN,64] = x[NN,128] @ W1[128,64].  W1 (32KB) in smem, 64 rows/block.
__global__ __launch_bounds__(256) void k_gemm1(const float* __restrict__ x,
                                               const float* __restrict__ W) {
    __shared__ float Ws[F1 * FH];     // 32 KB
    __shared__ float xs[4][F1];
    int tid = threadIdx.x;
    for (int i = tid; i < F1 * FH; i += 256) Ws[i] = W[i];
    int col = tid & 63;
    int rg  = tid >> 6;               // 0..3
    int row0 = blockIdx.x * 64;
    for (int rb = 0; rb < 64; rb += 4) {
        __syncthreads();
        for (int i = tid; i < 4 * F1; i += 256) {
            int r = i >> 7, c = i & 127;
            int row = row0 + rb + r;
            xs[r][c] = (row < NN) ? x[(long)row * F1 + c] : 0.f;
        }
        __syncthreads();
        int row = row0 + rb + rg;
        float acc = 0.f;
        #pragma unroll 16
        for (int k = 0; k < F1; k++) acc = fmaf(xs[rg][k], Ws[k * FH + col], acc);
        if (row < NN) g_h1[(long)row * FH + col] = acc;
    }
}

// Edge aggregation layer 1: one warp per edge, 64 features (2 per lane).
__global__ __launch_bounds__(256) void k_agg1(const int* __restrict__ ei, int E) {
    int warp = (blockIdx.x * blockDim.x + threadIdx.x) >> 5;
    int lane = threadIdx.x & 31;
    if (warp >= E) return;
    int s = ei[warp];
    int d = ei[E + warp];
    float norm = g_dinv[s] * g_dinv[d];
    const float* hs = &g_h1[(long)s * FH];
    float* ad = &g_a1[(long)d * FH];
    atomicAdd(&ad[lane],      hs[lane]      * norm);
    atomicAdd(&ad[lane + 32], hs[lane + 32] * norm);
}

// Self-loop + bias + ReLU (result stays in g_a1).
__global__ void k_fin1(const float* __restrict__ b1) {
    long i = blockIdx.x * (long)blockDim.x + threadIdx.x;
    if (i >= (long)NN * FH) return;
    int node = (int)(i >> 6);
    int c = (int)(i & 63);
    float di = g_dinv[node];
    float v = g_a1[i] + g_h1[i] * di * di + b1[c];
    g_a1[i] = fmaxf(v, 0.f);
}

// ---------------------------------------------------------------------------
// GEMM2: h3[NN,32] = a1[NN,64] @ W2[64,32].
__global__ __launch_bounds__(256) void k_gemm2(const float* __restrict__ W) {
    __shared__ float Ws[FH * FO];     // 8 KB
    __shared__ float xs[8][FH];
    int tid = threadIdx.x;
    for (int i = tid; i < FH * FO; i += 256) Ws[i] = W[i];
    int col = tid & 31;
    int rg  = tid >> 5;               // 0..7
    int row0 = blockIdx.x * 64;
    for (int rb = 0; rb < 64; rb += 8) {
        __syncthreads();
        for (int i = tid; i < 8 * FH; i += 256) {
            int r = i >> 6, c = i & 63;
            int row = row0 + rb + r;
            xs[r][c] = (row < NN) ? g_a1[(long)row * FH + c] : 0.f;
        }
        __syncthreads();
        int row = row0 + rb + rg;
        float acc = 0.f;
        #pragma unroll 16
        for (int k = 0; k < FH; k++) acc = fmaf(xs[rg][k], Ws[k * FO + col], acc);
        if (row < NN) g_h3[(long)row * FO + col] = acc;
    }
}

// Edge aggregation layer 2: one warp per edge, 32 features (1 per lane), into g_a2.
__global__ __launch_bounds__(256) void k_agg2(const int* __restrict__ ei, int E) {
    int warp = (blockIdx.x * blockDim.x + threadIdx.x) >> 5;
    int lane = threadIdx.x & 31;
    if (warp >= E) return;
    int s = ei[warp];
    int d = ei[E + warp];
    float norm = g_dinv[s] * g_dinv[d];
    atomicAdd(&g_a2[(long)d * FO + lane], g_h3[(long)s * FO + lane] * norm);
}

// Self-loop + bias; single plain store into d_out (no atomics on d_out).
__global__ void k_fin2(float* __restrict__ out, const float* __restrict__ b2) {
    long i = blockIdx.x * (long)blockDim.x + threadIdx.x;
    if (i >= (long)NN * FO) return;
    int node = (int)(i >> 5);
    int c = (int)(i & 31);
    float di = g_dinv[node];
    out[i] = g_a2[i] + g_h3[i] * di * di + b2[c];
}

// ---------------------------------------------------------------------------
extern "C" void kernel_launch(void* const* d_in, const int* in_sizes, int n_in,
                              void* d_out, int out_size) {
    const float* x  = (const float*)d_in[0];
    const int*   ei = (const int*)d_in[1];     // JAX default x64-disabled: int32
    const float* W1 = (const float*)d_in[2];
    const float* b1 = (const float*)d_in[3];
    const float* W2 = (const float*)d_in[4];
    const float* b2 = (const float*)d_in[5];
    float* out = (float*)d_out;

    const int E = in_sizes[1] / 2;

    k_init<<<2048, 256>>>();
    k_deg<<<(E + 255) / 256, 256>>>(ei, E);
    k_dinv<<<(NN + 255) / 256, 256>>>();

    k_gemm1<<<(NN + 63) / 64, 256>>>(x, W1);
    {
        long threads = (long)E * 32;
        k_agg1<<<(unsigned)((threads + 255) / 256), 256>>>(ei, E);
    }
    k_fin1<<<(unsigned)(((long)NN * FH + 255) / 256), 256>>>(b1);

    k_gemm2<<<(NN + 63) / 64, 256>>>(W2);
    {
        long threads = (long)E * 32;
        k_agg2<<<(unsigned)((threads + 255) / 256), 256>>>(ei, E);
    }
    k_fin2<<<(unsigned)(((long)NN * FO + 255) / 256), 256>>>(out, b2);
}

// round 4
// speedup vs baseline: 2.1510x; 2.1510x over previous
#include <cuda_runtime.h>
#include <cstdint>

#define NN 100000
#define F1 128
#define FH 64
#define FO 32

// Scratch (no allocations allowed).
__device__ int   g_deg[NN];
__device__ float g_dinv[NN];
__device__ float g_h1[(size_t)NN * FH];   // x @ W1
__device__ float g_a1[(size_t)NN * FH];   // aggregated layer-1 (relu'd in place)
__device__ float g_h3[(size_t)NN * FO];   // h2 @ W2
__device__ float g_a2[(size_t)NN * FO];   // aggregated layer-2

__device__ __forceinline__ void red_add_v4(float* addr, float4 v) {
    asm volatile("red.global.add.v4.f32 [%0], {%1,%2,%3,%4};"
                 :: "l"(addr), "f"(v.x), "f"(v.y), "f"(v.z), "f"(v.w) : "memory");
}

// ---------------------------------------------------------------------------
__global__ void k_init() {
    int stride = gridDim.x * blockDim.x;
    int i0 = blockIdx.x * blockDim.x + threadIdx.x;
    for (int j = i0; j < NN; j += stride) g_deg[j] = 0;
    float4 z = {0.f, 0.f, 0.f, 0.f};
    float4* a1 = (float4*)g_a1;
    float4* a2 = (float4*)g_a2;
    for (long j = i0; j < (long)NN * FH / 4; j += stride) a1[j] = z;
    for (long j = i0; j < (long)NN * FO / 4; j += stride) a2[j] = z;
}

__global__ void k_deg(const int* __restrict__ ei, int E) {
    int i = blockIdx.x * blockDim.x + threadIdx.x;
    if (i < E) atomicAdd(&g_deg[ei[E + i]], 1);
}

__global__ void k_dinv() {
    int i = blockIdx.x * blockDim.x + threadIdx.x;
    if (i < NN) g_dinv[i] = rsqrtf((float)g_deg[i] + 1.0f);  // +1 self-loop
}

// ---------------------------------------------------------------------------
// GEMM1: h1[NN,64] = x[NN,128] @ W1[128,64]. 32 rows/block, 2x4 register tile.
__global__ __launch_bounds__(256) void k_gemm1(const float* __restrict__ x,
                                               const float* __restrict__ W) {
    __shared__ float Ws[F1 * FH];   // 32 KB  [k][col]
    __shared__ float xs[32 * F1];   // 16 KB  [r][k]
    int tid = threadIdx.x;
    float4* Ws4 = (float4*)Ws;
    const float4* W4 = (const float4*)W;
    for (int i = tid; i < F1 * FH / 4; i += 256) Ws4[i] = W4[i];
    int row0 = blockIdx.x * 32;     // NN = 3125*32 exactly
    const float4* x4 = (const float4*)(x + (size_t)row0 * F1);
    float4* xs4 = (float4*)xs;
    for (int i = tid; i < 32 * F1 / 4; i += 256) xs4[i] = x4[i];
    __syncthreads();

    int tx = tid & 15;              // cols 4tx..4tx+3
    int ty = tid >> 4;              // rows 2ty, 2ty+1
    const float* xr0 = xs + (2 * ty) * F1;
    const float* xr1 = xs + (2 * ty + 1) * F1;
    float4 acc0 = {0, 0, 0, 0}, acc1 = {0, 0, 0, 0};
    #pragma unroll 8
    for (int k = 0; k < F1; k++) {
        float4 w = Ws4[k * 16 + tx];
        float a0 = xr0[k], a1 = xr1[k];
        acc0.x = fmaf(a0, w.x, acc0.x); acc0.y = fmaf(a0, w.y, acc0.y);
        acc0.z = fmaf(a0, w.z, acc0.z); acc0.w = fmaf(a0, w.w, acc0.w);
        acc1.x = fmaf(a1, w.x, acc1.x); acc1.y = fmaf(a1, w.y, acc1.y);
        acc1.z = fmaf(a1, w.z, acc1.z); acc1.w = fmaf(a1, w.w, acc1.w);
    }
    float4* h1v = (float4*)g_h1;
    h1v[(size_t)(row0 + 2 * ty) * 16 + tx]     = acc0;
    h1v[(size_t)(row0 + 2 * ty + 1) * 16 + tx] = acc1;
}

// Edge aggregation layer 1: 16 threads/edge, one float4 chunk + v4 RED each.
__global__ __launch_bounds__(256) void k_agg1(const int* __restrict__ ei, int E) {
    long gid = blockIdx.x * (long)blockDim.x + threadIdx.x;
    long e = gid >> 4;
    if (e >= E) return;
    int chunk = (int)(gid & 15);
    int s = ei[e];
    int d = ei[E + e];
    float norm = g_dinv[s] * g_dinv[d];
    float4 h = ((const float4*)g_h1)[(size_t)s * 16 + chunk];
    float4 m = {h.x * norm, h.y * norm, h.z * norm, h.w * norm};
    red_add_v4(&g_a1[(size_t)d * FH + chunk * 4], m);
}

// Self-loop + bias + ReLU (in place in g_a1), float4.
__global__ void k_fin1(const float* __restrict__ b1) {
    long i = blockIdx.x * (long)blockDim.x + threadIdx.x;
    if (i >= (long)NN * FH / 4) return;
    int node = (int)(i >> 4);
    int c4 = (int)(i & 15);
    float di = g_dinv[node];
    float w = di * di;
    float4 a = ((float4*)g_a1)[i];
    float4 h = ((const float4*)g_h1)[i];
    float4 b = ((const float4*)b1)[c4];
    a.x = fmaxf(fmaf(h.x, w, a.x) + b.x, 0.f);
    a.y = fmaxf(fmaf(h.y, w, a.y) + b.y, 0.f);
    a.z = fmaxf(fmaf(h.z, w, a.z) + b.z, 0.f);
    a.w = fmaxf(fmaf(h.w, w, a.w) + b.w, 0.f);
    ((float4*)g_a1)[i] = a;
}

// ---------------------------------------------------------------------------
// GEMM2: h3[NN,32] = a1[NN,64] @ W2[64,32]. 64 rows/block, 2x4 register tile.
__global__ __launch_bounds__(256) void k_gemm2(const float* __restrict__ W) {
    __shared__ float Ws[FH * FO];   // 8 KB
    __shared__ float xs[64 * FH];   // 16 KB
    int tid = threadIdx.x;
    float4* Ws4 = (float4*)Ws;
    const float4* W4 = (const float4*)W;
    for (int i = tid; i < FH * FO / 4; i += 256) Ws4[i] = W4[i];
    int row0 = blockIdx.x * 64;
    float4* xs4 = (float4*)xs;
    const float4* x4 = (const float4*)g_a1;
    for (int i = tid; i < 64 * FH / 4; i += 256) {
        int r = i >> 4;             // 16 float4 per row
        int row = row0 + r;
        xs4[i] = (row < NN) ? x4[(size_t)row * 16 + (i & 15)]
                            : make_float4(0.f, 0.f, 0.f, 0.f);
    }
    __syncthreads();

    int tx = tid & 7;               // cols 4tx..4tx+3
    int ty = tid >> 3;              // rows 2ty, 2ty+1
    const float* xr0 = xs + (2 * ty) * FH;
    const float* xr1 = xs + (2 * ty + 1) * FH;
    float4 acc0 = {0, 0, 0, 0}, acc1 = {0, 0, 0, 0};
    #pragma unroll 8
    for (int k = 0; k < FH; k++) {
        float4 w = Ws4[k * 8 + tx];
        float a0 = xr0[k], a1 = xr1[k];
        acc0.x = fmaf(a0, w.x, acc0.x); acc0.y = fmaf(a0, w.y, acc0.y);
        acc0.z = fmaf(a0, w.z, acc0.z); acc0.w = fmaf(a0, w.w, acc0.w);
        acc1.x = fmaf(a1, w.x, acc1.x); acc1.y = fmaf(a1, w.y, acc1.y);
        acc1.z = fmaf(a1, w.z, acc1.z); acc1.w = fmaf(a1, w.w, acc1.w);
    }
    int r0 = row0 + 2 * ty, r1 = r0 + 1;
    float4* h3v = (float4*)g_h3;
    if (r0 < NN) h3v[(size_t)r0 * 8 + tx] = acc0;
    if (r1 < NN) h3v[(size_t)r1 * 8 + tx] = acc1;
}

// Edge aggregation layer 2: 8 threads/edge, one float4 chunk + v4 RED each.
__global__ __launch_bounds__(256) void k_agg2(const int* __restrict__ ei, int E) {
    long gid = blockIdx.x * (long)blockDim.x + threadIdx.x;
    long e = gid >> 3;
    if (e >= E) return;
    int chunk = (int)(gid & 7);
    int s = ei[e];
    int d = ei[E + e];
    float norm = g_dinv[s] * g_dinv[d];
    float4 h = ((const float4*)g_h3)[(size_t)s * 8 + chunk];
    float4 m = {h.x * norm, h.y * norm, h.z * norm, h.w * norm};
    red_add_v4(&g_a2[(size_t)d * FO + chunk * 4], m);
}

// Self-loop + bias; plain float4 store into d_out.
__global__ void k_fin2(float* __restrict__ out, const float* __restrict__ b2) {
    long i = blockIdx.x * (long)blockDim.x + threadIdx.x;
    if (i >= (long)NN * FO / 4) return;
    int node = (int)(i >> 3);
    int c4 = (int)(i & 7);
    float di = g_dinv[node];
    float w = di * di;
    float4 a = ((const float4*)g_a2)[i];
    float4 h = ((const float4*)g_h3)[i];
    float4 b = ((const float4*)b2)[c4];
    a.x = fmaf(h.x, w, a.x) + b.x;
    a.y = fmaf(h.y, w, a.y) + b.y;
    a.z = fmaf(h.z, w, a.z) + b.z;
    a.w = fmaf(h.w, w, a.w) + b.w;
    ((float4*)out)[i] = a;
}

// ---------------------------------------------------------------------------
extern "C" void kernel_launch(void* const* d_in, const int* in_sizes, int n_in,
                              void* d_out, int out_size) {
    const float* x  = (const float*)d_in[0];
    const int*   ei = (const int*)d_in[1];     // int32 (JAX x64 disabled)
    const float* W1 = (const float*)d_in[2];
    const float* b1 = (const float*)d_in[3];
    const float* W2 = (const float*)d_in[4];
    const float* b2 = (const float*)d_in[5];
    float* out = (float*)d_out;

    const int E = in_sizes[1] / 2;

    k_init<<<2048, 256>>>();
    k_deg<<<(E + 255) / 256, 256>>>(ei, E);
    k_dinv<<<(NN + 255) / 256, 256>>>();

    k_gemm1<<<NN / 32, 256>>>(x, W1);
    k_agg1<<<(unsigned)(((long)E * 16 + 255) / 256), 256>>>(ei, E);
    k_fin1<<<(unsigned)(((long)NN * FH / 4 + 255) / 256), 256>>>(b1);

    k_gemm2<<<(NN + 63) / 64, 256>>>(W2);
    k_agg2<<<(unsigned)(((long)E * 8 + 255) / 256), 256>>>(ei, E);
    k_fin2<<<(unsigned)(((long)NN * FO / 4 + 255) / 256), 256>>>(out, b2);
}

// round 5
// speedup vs baseline: 2.7819x; 1.2933x over previous
#include <cuda_runtime.h>
#include <cstdint>

#define NN 100000
#define F1 128
#define FH 64
#define FO 32
#define EMAX 1600000
#define NSCAN_BLK 196            // ceil(100000/512)

// Scratch (no allocations allowed).
__device__ int   g_deg[NN];
__device__ int   g_cur[NN];
__device__ int   g_off[NN];
__device__ int   g_scan[NN];
__device__ int   g_bsum[NSCAN_BLK];
__device__ int   g_bsumx[NSCAN_BLK];
__device__ float g_dinv[NN];
__device__ int2  g_edge[EMAX];            // (src, norm) grouped by dst
__device__ float g_h1[(size_t)NN * FH];   // x @ W1
__device__ float g_a1[(size_t)NN * FH];   // layer-1 activations (post ReLU)
__device__ float g_h3[(size_t)NN * FO];   // a1 @ W2

// ---------------------------------------------------------------------------
__global__ void k_init() {
    int i = blockIdx.x * blockDim.x + threadIdx.x;
    if (i < NN) g_deg[i] = 0;
}

__global__ void k_deg(const int* __restrict__ ei, int E) {
    int i = blockIdx.x * blockDim.x + threadIdx.x;
    if (i < E) atomicAdd(&g_deg[ei[E + i]], 1);
}

__global__ void k_dinv() {
    int i = blockIdx.x * blockDim.x + threadIdx.x;
    if (i < NN) g_dinv[i] = rsqrtf((float)g_deg[i] + 1.0f);  // +1 self-loop
}

// ---- exclusive prefix sum of g_deg -> g_off (3 small kernels) --------------
__global__ __launch_bounds__(512) void k_scan1() {
    __shared__ int sh[512];
    int t = threadIdx.x;
    int i = blockIdx.x * 512 + t;
    int v = (i < NN) ? g_deg[i] : 0;
    sh[t] = v;
    for (int d = 1; d < 512; d <<= 1) {
        __syncthreads();
        int u = (t >= d) ? sh[t - d] : 0;
        __syncthreads();
        sh[t] += u;
    }
    __syncthreads();
    if (i < NN) g_scan[i] = sh[t];
    if (t == 511) g_bsum[blockIdx.x] = sh[511];
}

__global__ __launch_bounds__(256) void k_scan2() {
    __shared__ int sh[256];
    int t = threadIdx.x;
    int v = (t < NSCAN_BLK) ? g_bsum[t] : 0;
    sh[t] = v;
    for (int d = 1; d < 256; d <<= 1) {
        __syncthreads();
        int u = (t >= d) ? sh[t - d] : 0;
        __syncthreads();
        sh[t] += u;
    }
    __syncthreads();
    if (t < NSCAN_BLK) g_bsumx[t] = sh[t] - v;   // exclusive
}

__global__ void k_scan3() {
    int i = blockIdx.x * blockDim.x + threadIdx.x;
    if (i >= NN) return;
    g_off[i] = g_scan[i] - g_deg[i] + g_bsumx[i >> 9];  // exclusive offset
    g_cur[i] = 0;
}

// Scatter edges into destination-grouped order, packing (src, norm).
__global__ void k_scatter(const int* __restrict__ ei, int E) {
    int e = blockIdx.x * blockDim.x + threadIdx.x;
    if (e >= E) return;
    int s = ei[e];
    int d = ei[E + e];
    float norm = g_dinv[s] * g_dinv[d];
    int pos = g_off[d] + atomicAdd(&g_cur[d], 1);
    g_edge[pos] = make_int2(s, __float_as_int(norm));
}

// ---------------------------------------------------------------------------
// GEMM1: h1[NN,64] = x[NN,128] @ W1[128,64]. 64 rows/block, 4x4 register tile.
__global__ __launch_bounds__(256) void k_gemm1(const float* __restrict__ x,
                                               const float* __restrict__ W) {
    __shared__ float Ws[F1 * FH];   // 32 KB  [k][col]
    __shared__ float xs[64 * F1];   // 32 KB  [r][k]
    int tid = threadIdx.x;
    float4* Ws4 = (float4*)Ws;
    const float4* W4 = (const float4*)W;
    for (int i = tid; i < F1 * FH / 4; i += 256) Ws4[i] = W4[i];
    int row0 = blockIdx.x * 64;
    const float4* x4 = (const float4*)x;
    float4* xs4 = (float4*)xs;
    for (int i = tid; i < 64 * F1 / 4; i += 256) {
        int row = row0 + (i >> 5);                 // 32 float4 per row
        xs4[i] = (row < NN) ? x4[(size_t)row * 32 + (i & 31)]
                            : make_float4(0.f, 0.f, 0.f, 0.f);
    }
    __syncthreads();

    int tx = tid & 15;              // cols 4tx..4tx+3
    int ty = tid >> 4;              // rows 4ty..4ty+3
    const float* xr = xs + 4 * ty * F1;
    float4 acc[4] = {{0,0,0,0},{0,0,0,0},{0,0,0,0},{0,0,0,0}};
    #pragma unroll 4
    for (int k = 0; k < F1; k++) {
        float4 w = Ws4[k * 16 + tx];
        #pragma unroll
        for (int j = 0; j < 4; j++) {
            float a = xr[j * F1 + k];
            acc[j].x = fmaf(a, w.x, acc[j].x);
            acc[j].y = fmaf(a, w.y, acc[j].y);
            acc[j].z = fmaf(a, w.z, acc[j].z);
            acc[j].w = fmaf(a, w.w, acc[j].w);
        }
    }
    float4* h1v = (float4*)g_h1;
    #pragma unroll
    for (int j = 0; j < 4; j++) {
        int row = row0 + 4 * ty + j;
        if (row < NN) h1v[(size_t)row * 16 + tx] = acc[j];
    }
}

// Aggregation layer 1 (+ self-loop + bias + ReLU): one warp per dst node.
__global__ __launch_bounds__(256) void k_agg1(const float* __restrict__ b1) {
    int node = (blockIdx.x * 256 + threadIdx.x) >> 5;
    int lane = threadIdx.x & 31;
    if (node >= NN) return;
    int off = g_off[node];
    int n   = g_deg[node];
    const float2* h1v = (const float2*)g_h1;
    float2 acc = make_float2(0.f, 0.f);
    int i = 0;
    for (; i + 1 < n; i += 2) {
        int2 e0 = g_edge[off + i];
        int2 e1 = g_edge[off + i + 1];
        float2 p = h1v[(size_t)e0.x * 32 + lane];
        float2 q = h1v[(size_t)e1.x * 32 + lane];
        float n0 = __int_as_float(e0.y), n1 = __int_as_float(e1.y);
        acc.x = fmaf(p.x, n0, acc.x); acc.y = fmaf(p.y, n0, acc.y);
        acc.x = fmaf(q.x, n1, acc.x); acc.y = fmaf(q.y, n1, acc.y);
    }
    if (i < n) {
        int2 e0 = g_edge[off + i];
        float2 p = h1v[(size_t)e0.x * 32 + lane];
        float n0 = __int_as_float(e0.y);
        acc.x = fmaf(p.x, n0, acc.x); acc.y = fmaf(p.y, n0, acc.y);
    }
    float di = g_dinv[node], w = di * di;
    float2 hs = h1v[(size_t)node * 32 + lane];
    float2 bb = ((const float2*)b1)[lane];
    acc.x = fmaxf(fmaf(hs.x, w, acc.x) + bb.x, 0.f);
    acc.y = fmaxf(fmaf(hs.y, w, acc.y) + bb.y, 0.f);
    ((float2*)g_a1)[(size_t)node * 32 + lane] = acc;
}

// ---------------------------------------------------------------------------
// GEMM2: h3[NN,32] = a1[NN,64] @ W2[64,32]. 128 rows/block, 4x4 register tile.
__global__ __launch_bounds__(256) void k_gemm2(const float* __restrict__ W) {
    __shared__ float Ws[FH * FO];    // 8 KB
    __shared__ float xs[128 * FH];   // 32 KB
    int tid = threadIdx.x;
    float4* Ws4 = (float4*)Ws;
    const float4* W4 = (const float4*)W;
    for (int i = tid; i < FH * FO / 4; i += 256) Ws4[i] = W4[i];
    int row0 = blockIdx.x * 128;
    const float4* x4 = (const float4*)g_a1;
    float4* xs4 = (float4*)xs;
    for (int i = tid; i < 128 * FH / 4; i += 256) {
        int row = row0 + (i >> 4);                 // 16 float4 per row
        xs4[i] = (row < NN) ? x4[(size_t)row * 16 + (i & 15)]
                            : make_float4(0.f, 0.f, 0.f, 0.f);
    }
    __syncthreads();

    int tx = tid & 7;               // cols 4tx..4tx+3
    int ty = tid >> 3;              // rows 4ty..4ty+3
    const float* xr = xs + 4 * ty * FH;
    float4 acc[4] = {{0,0,0,0},{0,0,0,0},{0,0,0,0},{0,0,0,0}};
    #pragma unroll 4
    for (int k = 0; k < FH; k++) {
        float4 w = Ws4[k * 8 + tx];
        #pragma unroll
        for (int j = 0; j < 4; j++) {
            float a = xr[j * FH + k];
            acc[j].x = fmaf(a, w.x, acc[j].x);
            acc[j].y = fmaf(a, w.y, acc[j].y);
            acc[j].z = fmaf(a, w.z, acc[j].z);
            acc[j].w = fmaf(a, w.w, acc[j].w);
        }
    }
    float4* h3v = (float4*)g_h3;
    #pragma unroll
    for (int j = 0; j < 4; j++) {
        int row = row0 + 4 * ty + j;
        if (row < NN) h3v[(size_t)row * 8 + tx] = acc[j];
    }
}

// Aggregation layer 2 (+ self-loop + bias): one warp per dst node, writes d_out.
__global__ __launch_bounds__(256) void k_agg2(float* __restrict__ out,
                                              const float* __restrict__ b2) {
    int node = (blockIdx.x * 256 + threadIdx.x) >> 5;
    int lane = threadIdx.x & 31;
    if (node >= NN) return;
    int off = g_off[node];
    int n   = g_deg[node];
    float acc = 0.f;
    int i = 0;
    for (; i + 1 < n; i += 2) {
        int2 e0 = g_edge[off + i];
        int2 e1 = g_edge[off + i + 1];
        float p = g_h3[(size_t)e0.x * 32 + lane];
        float q = g_h3[(size_t)e1.x * 32 + lane];
        acc = fmaf(p, __int_as_float(e0.y), acc);
        acc = fmaf(q, __int_as_float(e1.y), acc);
    }
    if (i < n) {
        int2 e0 = g_edge[off + i];
        acc = fmaf(g_h3[(size_t)e0.x * 32 + lane], __int_as_float(e0.y), acc);
    }
    float di = g_dinv[node], w = di * di;
    out[(size_t)node * 32 + lane] =
        fmaf(g_h3[(size_t)node * 32 + lane], w, acc) + b2[lane];
}

// ---------------------------------------------------------------------------
extern "C" void kernel_launch(void* const* d_in, const int* in_sizes, int n_in,
                              void* d_out, int out_size) {
    const float* x  = (const float*)d_in[0];
    const int*   ei = (const int*)d_in[1];     // int32 (JAX x64 disabled)
    const float* W1 = (const float*)d_in[2];
    const float* b1 = (const float*)d_in[3];
    const float* W2 = (const float*)d_in[4];
    const float* b2 = (const float*)d_in[5];
    float* out = (float*)d_out;

    const int E = in_sizes[1] / 2;

    k_init<<<(NN + 255) / 256, 256>>>();
    k_deg<<<(E + 255) / 256, 256>>>(ei, E);
    k_dinv<<<(NN + 255) / 256, 256>>>();
    k_scan1<<<NSCAN_BLK, 512>>>();
    k_scan2<<<1, 256>>>();
    k_scan3<<<(NN + 255) / 256, 256>>>();
    k_scatter<<<(E + 255) / 256, 256>>>(ei, E);

    k_gemm1<<<(NN + 63) / 64, 256>>>(x, W1);
    k_agg1<<<(NN * 32 + 255) / 256, 256>>>(b1);

    k_gemm2<<<(NN + 127) / 128, 256>>>(W2);
    k_agg2<<<(NN * 32 + 255) / 256, 256>>>(out, b2);
}